// round 13
// baseline (speedup 1.0000x reference)
#include <cuda_runtime.h>
#include <math.h>
#include <stdint.h>

// ---------------- problem constants ----------------
#define NB     8
#define CIN    256
#define HH     128
#define WW     128
#define HWD    16384            // HH*WW
#define NHW    131072           // NB*HWD
#define C2     128
#define GR     8
#define C2G    16               // C2/GR
#define SH     64               // sp spatial
#define SHW    4096             // 64*64

// ---------------- scratch (device globals; no allocs allowed) ----------------
__device__ float g_sp_t[NB * SHW * CIN];        // sp  NHWC (sampler path)
__device__ float g_cp_t[NB * HWD * CIN];        // cp  NHWC (sampler)
__device__ float g_spup_t[NB * HWD * CIN];      // sp_up NHWC (sampler)
__device__ float g_z[NB * C2 * SHW];            // low-res conv_bn(sp) affine
__device__ float g_cp1[NB * C2 * HWD];          // NCHW
__device__ float g_sp1[NB * C2 * HWD];
__device__ float g_redim[NB * C2 * HWD];
__device__ float g_sim[NB * GR * HWD];
__device__ float g_fdif[NB * C2 * HWD];
__device__ float g_fdir[NB * 32 * HWD];
__device__ float g_fdist[NB * 32 * HWD];
__device__ float g_wofft[192 * 32];             // w_off transposed [ci][co]

// ---------------- cp.async helpers ----------------
__device__ __forceinline__ void cp_async16(float* dst, const float* src) {
    uint32_t a = (uint32_t)__cvta_generic_to_shared(dst);
    asm volatile("cp.async.cg.shared.global [%0], [%1], 16;" :: "r"(a), "l"(src));
}
__device__ __forceinline__ void cp_async4_zf(float* dst, const float* src, bool valid) {
    uint32_t a = (uint32_t)__cvta_generic_to_shared(dst);
    int sz = valid ? 4 : 0;
    asm volatile("cp.async.ca.shared.global [%0], [%1], 4, %2;" :: "r"(a), "l"(src), "r"(sz));
}
__device__ __forceinline__ void cp_async4(float* dst, const float* src) {
    uint32_t a = (uint32_t)__cvta_generic_to_shared(dst);
    asm volatile("cp.async.ca.shared.global [%0], [%1], 4;" :: "r"(a), "l"(src));
}
#define CP_COMMIT() asm volatile("cp.async.commit_group;" ::: "memory")
#define CP_WAIT0()  asm volatile("cp.async.wait_group 0;" ::: "memory")

// ---------------- transpose NCHW -> NHWC ----------------
__global__ void transpose_kernel(const float* __restrict__ in, float* __restrict__ out,
                                 int C, int HW) {
    __shared__ float tile[32][33];
    int hwb = blockIdx.x * 32, cb = blockIdx.y * 32, n = blockIdx.z;
    int lane = threadIdx.x & 31, row = threadIdx.x >> 5;
    #pragma unroll
    for (int r = row; r < 32; r += 8)
        tile[r][lane] = in[(size_t)(n * C + cb + r) * HW + hwb + lane];
    __syncthreads();
    #pragma unroll
    for (int r = row; r < 32; r += 8)
        out[((size_t)n * HW + hwb + r) * C + cb + lane] = tile[lane][r];
}

// ---------------- transpose w_off [32][192] -> [192][32] ----------------
__global__ void woff_transpose_kernel(const float* __restrict__ w, float* __restrict__ wt) {
    int i = blockIdx.x * 256 + threadIdx.x;
    if (i < 32 * 192) {
        int co = i / 192, ci = i - co * 192;
        wt[ci * 32 + co] = w[i];
    }
}

// ---------------- bilinear upsample (align_corners) in NHWC (sampler source) ----------------
__global__ void upsample_kernel(const float* __restrict__ sp_t, float* __restrict__ out_t) {
    int idx = blockIdx.x * 256 + threadIdx.x;
    int c4 = idx & 63;
    int p  = idx >> 6;
    int hw = p & (HWD - 1);
    int n  = p >> 14;
    int oy = hw >> 7, ox = hw & 127;
    float sy = oy * (63.0f / 127.0f);
    float sx = ox * (63.0f / 127.0f);
    int y0 = (int)sy; float wy = sy - (float)y0; int y1 = min(y0 + 1, 63);
    int x0 = (int)sx; float wx = sx - (float)x0; int x1 = min(x0 + 1, 63);
    const float4* s = (const float4*)sp_t;
    size_t b = (size_t)n * SHW;
    float4 v00 = s[(b + y0 * 64 + x0) * 64 + c4];
    float4 v01 = s[(b + y0 * 64 + x1) * 64 + c4];
    float4 v10 = s[(b + y1 * 64 + x0) * 64 + c4];
    float4 v11 = s[(b + y1 * 64 + x1) * 64 + c4];
    float w00 = (1.f - wy) * (1.f - wx), w01 = (1.f - wy) * wx;
    float w10 = wy * (1.f - wx),         w11 = wy * wx;
    float4 r;
    r.x = v00.x * w00 + v01.x * w01 + v10.x * w10 + v11.x * w11;
    r.y = v00.y * w00 + v01.y * w01 + v10.y * w10 + v11.y * w11;
    r.z = v00.z * w00 + v01.z * w01 + v10.z * w10 + v11.z * w11;
    r.w = v00.w * w00 + v01.w * w01 + v10.w * w10 + v11.w * w11;
    ((float4*)out_t)[(size_t)p * 64 + c4] = r;
}

// ---------------- bilinear upsample NCHW + ReLU (sp1 = relu(interp(z))) ----------------
__global__ void upsample_relu_kernel(const float* __restrict__ z, float* __restrict__ out) {
    int idx = blockIdx.x * 256 + threadIdx.x;
    int hw = idx & (HWD - 1);
    int nc = idx >> 14;
    int oy = hw >> 7, ox = hw & 127;
    float sy = oy * (63.0f / 127.0f);
    float sx = ox * (63.0f / 127.0f);
    int y0 = (int)sy; float wy = sy - (float)y0; int y1 = min(y0 + 1, 63);
    int x0 = (int)sx; float wx = sx - (float)x0; int x1 = min(x0 + 1, 63);
    const float* b = z + ((size_t)nc << 12);
    float v = (b[y0 * 64 + x0] * (1.f - wx) + b[y0 * 64 + x1] * wx) * (1.f - wy)
            + (b[y1 * 64 + x0] * (1.f - wx) + b[y1 * 64 + x1] * wx) * wy;
    out[idx] = fmaxf(v, 0.f);
}

// ---------------- 1x1 conv as SGEMM (NCHW) ----------------
__global__ __launch_bounds__(256, 2)
void conv1x1_kernel(const float* __restrict__ in0, const float* __restrict__ in1,
                    int ci0, int CI, int hwshift, const float* __restrict__ Wt,
                    const float* __restrict__ gamma, const float* __restrict__ beta,
                    int relu, float* __restrict__ out, int CO) {
    __shared__ __align__(16) float As[2][16][132];
    __shared__ __align__(16) float Bs[2][16][132];
    int t   = threadIdx.x;
    int qb  = blockIdx.x * 128;
    int cob = blockIdx.y * 128;
    int hwmask = (1 << hwshift) - 1;
    int n   = qb >> hwshift;
    int hwb = qb & hwmask;
    int tc  = (t & 15) * 8;
    int tr  = (t >> 4) * 8;
    int a_co = t >> 1, a_kq = (t & 1) * 8;
    int b_k  = t >> 4, b_px = (t & 15) * 8;

    float acc[8][8];
    #pragma unroll
    for (int i = 0; i < 8; i++)
        #pragma unroll
        for (int j = 0; j < 8; j++) acc[i][j] = 0.f;

    {
        int ci = b_k;
        const float* s0 = (ci < ci0)
            ? &in0[(((size_t)(n * ci0 + ci)) << hwshift) + hwb + b_px]
            : &in1[(((size_t)(n * (CI - ci0) + (ci - ci0))) << hwshift) + hwb + b_px];
        cp_async16(&Bs[0][b_k][b_px], s0);
        cp_async16(&Bs[0][b_k][b_px + 4], s0 + 4);
        CP_COMMIT();
    }
    float4 ra0 = *(const float4*)&Wt[(size_t)(cob + a_co) * CI + a_kq];
    float4 ra1 = *(const float4*)&Wt[(size_t)(cob + a_co) * CI + a_kq + 4];

    int s = 0;
    for (int kb = 0; kb < CI; kb += 16, s ^= 1) {
        As[s][a_kq + 0][a_co] = ra0.x; As[s][a_kq + 1][a_co] = ra0.y;
        As[s][a_kq + 2][a_co] = ra0.z; As[s][a_kq + 3][a_co] = ra0.w;
        As[s][a_kq + 4][a_co] = ra1.x; As[s][a_kq + 5][a_co] = ra1.y;
        As[s][a_kq + 6][a_co] = ra1.z; As[s][a_kq + 7][a_co] = ra1.w;
        CP_WAIT0();
        __syncthreads();
        int kn = kb + 16;
        if (kn < CI) {
            int ci = kn + b_k;
            const float* sn = (ci < ci0)
                ? &in0[(((size_t)(n * ci0 + ci)) << hwshift) + hwb + b_px]
                : &in1[(((size_t)(n * (CI - ci0) + (ci - ci0))) << hwshift) + hwb + b_px];
            cp_async16(&Bs[s ^ 1][b_k][b_px], sn);
            cp_async16(&Bs[s ^ 1][b_k][b_px + 4], sn + 4);
            CP_COMMIT();
            ra0 = *(const float4*)&Wt[(size_t)(cob + a_co) * CI + kn + a_kq];
            ra1 = *(const float4*)&Wt[(size_t)(cob + a_co) * CI + kn + a_kq + 4];
        }
        #pragma unroll
        for (int k = 0; k < 16; k++) {
            float4 a0 = *(const float4*)&As[s][k][tr];
            float4 a1 = *(const float4*)&As[s][k][tr + 4];
            float4 b0 = *(const float4*)&Bs[s][k][tc];
            float4 b1 = *(const float4*)&Bs[s][k][tc + 4];
            float av[8] = {a0.x, a0.y, a0.z, a0.w, a1.x, a1.y, a1.z, a1.w};
            float bv[8] = {b0.x, b0.y, b0.z, b0.w, b1.x, b1.y, b1.z, b1.w};
            #pragma unroll
            for (int i = 0; i < 8; i++)
                #pragma unroll
                for (int j = 0; j < 8; j++)
                    acc[i][j] += av[i] * bv[j];
        }
    }

    const float rs = 1.0f / sqrtf(1.0f + 1e-5f);
    #pragma unroll
    for (int i = 0; i < 8; i++) {
        int co = cob + tr + i;
        float sc = 1.f, bi;
        if (gamma) { sc = gamma[co] * rs; bi = beta[co]; } else { bi = beta[co]; }
        float r[8];
        #pragma unroll
        for (int j = 0; j < 8; j++) {
            float v = acc[i][j];
            if (gamma) { v = v * sc + bi; if (relu > 0) v = fmaxf(v, 0.f); }
            else v += bi;
            r[j] = v;
        }
        float* dst = &out[(((size_t)(n * CO + co)) << hwshift) + hwb + tc];
        *(float4*)dst       = make_float4(r[0], r[1], r[2], r[3]);
        *(float4*)(dst + 4) = make_float4(r[4], r[5], r[6], r[7]);
    }
}

// ---------------- grouped cosine sim + |cp1-sp1| ----------------
__global__ void simfdif_kernel(const float* __restrict__ cp1, const float* __restrict__ sp1,
                               float* __restrict__ fdif, float* __restrict__ sim) {
    int idx = blockIdx.x * 256 + threadIdx.x;
    int hw = idx & (HWD - 1);
    int ng = idx >> 14;
    int gi = ng & 7, n = ng >> 3;
    size_t base = (size_t)((n * C2 + gi * C2G) << 14) + hw;
    float num = 0.f, na = 0.f, nb = 0.f;
    #pragma unroll
    for (int c = 0; c < C2G; c++) {
        float a = cp1[base + ((size_t)c << 14)];
        float b = sp1[base + ((size_t)c << 14)];
        num += a * b; na += a * a; nb += b * b;
        fdif[base + ((size_t)c << 14)] = fabsf(a - b);
    }
    sim[((size_t)ng << 14) + hw] =
        num / (fmaxf(sqrtf(na), 1e-8f) * fmaxf(sqrtf(nb), 1e-8f));
}

// ---------------- 3x3 conv, pad 1, CO=32 — cp.async zfill, 8-ci stages ----------------
// grid: (W/32, H/8, NB); 256 threads: 64 pixel-quads x 4 co-octets
#define PS8 (8 * 10 * 34)   // 2720
#define WS8 (8 * 32 * 9)    // 2304
__global__ void conv3x3_kernel(const float* __restrict__ in, const float* __restrict__ wgt,
                               const float* __restrict__ bias, float* __restrict__ out, int CI) {
    __shared__ float ps[2][8][10][36];
    __shared__ __align__(16) float ws[2][8][9][32];
    int t  = threadIdx.x;
    int o  = t >> 6;
    int q  = t & 63;
    int ty = q >> 3;
    int tx = (q & 7) * 4;
    int n  = blockIdx.z;
    int y0 = blockIdx.y * 8, x0 = blockIdx.x * 32;
    float acc[8][4];
    #pragma unroll
    for (int a = 0; a < 8; a++)
        #pragma unroll
        for (int b = 0; b < 4; b++) acc[a][b] = 0.f;

    // async stage loader (8 channels at cbase into buffer st)
    auto stage = [&](int st, int cbase) {
        for (int i = t; i < PS8; i += 256) {
            int cc = i / 340; int rem = i - cc * 340;
            int yy = rem / 34; int xx = rem - yy * 34;
            int gy = y0 + yy - 1, gx = x0 + xx - 1;
            bool valid = (gy >= 0) & (gy < HH) & (gx >= 0) & (gx < WW);
            int cy = min(max(gy, 0), HH - 1), cx = min(max(gx, 0), WW - 1);
            cp_async4_zf(&ps[st][cc][yy][xx],
                         &in[(size_t)((n * CI + cbase + cc) << 14) + (cy << 7) + cx], valid);
        }
        for (int i = t; i < WS8; i += 256) {
            int cc = i / 288; int rem = i - cc * 288;
            int tap = rem >> 5; int co = rem & 31;
            cp_async4(&ws[st][cc][tap][co],
                      &wgt[(size_t)(co * CI + cbase + cc) * 9 + tap]);
        }
        CP_COMMIT();
    };

    stage(0, 0);
    int s = 0;
    for (int cb = 0; cb < CI; cb += 8, s ^= 1) {
        CP_WAIT0();
        __syncthreads();
        if (cb + 8 < CI) stage(s ^ 1, cb + 8);
        #pragma unroll
        for (int cc = 0; cc < 8; cc++) {
            float p[3][6];
            #pragma unroll
            for (int yy = 0; yy < 3; yy++)
                #pragma unroll
                for (int xx = 0; xx < 6; xx++)
                    p[yy][xx] = ps[s][cc][ty + yy][tx + xx];
            #pragma unroll
            for (int tap = 0; tap < 9; tap++) {
                int ky = tap / 3, kx = tap - ky * 3;
                float4 w0 = *(const float4*)&ws[s][cc][tap][o * 8];
                float4 w1 = *(const float4*)&ws[s][cc][tap][o * 8 + 4];
                float wv[8] = {w0.x, w0.y, w0.z, w0.w, w1.x, w1.y, w1.z, w1.w};
                #pragma unroll
                for (int c8 = 0; c8 < 8; c8++) {
                    acc[c8][0] += wv[c8] * p[ky][kx + 0];
                    acc[c8][1] += wv[c8] * p[ky][kx + 1];
                    acc[c8][2] += wv[c8] * p[ky][kx + 2];
                    acc[c8][3] += wv[c8] * p[ky][kx + 3];
                }
            }
        }
        __syncthreads();
    }
    #pragma unroll
    for (int c8 = 0; c8 < 8; c8++) {
        int co = o * 8 + c8;
        float b = bias[co];
        size_t ob = (size_t)((n * 32 + co) << 14) + ((y0 + ty) << 7) + x0 + tx;
        #pragma unroll
        for (int j = 0; j < 4; j++) out[ob + j] = acc[c8][j] + b;
    }
}

// ---------------- fused off 1x1 conv + dual grid_sample (64-px tile) ----------------
__device__ __forceinline__ float4 sample32(const float* __restrict__ src_t, int n,
                                           int chan4, float gx, float gy) {
    float x0f = floorf(gx), y0f = floorf(gy);
    int x0 = (int)x0f, y0 = (int)y0f;
    float wx = gx - x0f, wy = gy - y0f;
    bool vx0 = (x0 >= 0) & (x0 <= WW - 1);
    bool vx1 = (x0 + 1 >= 0) & (x0 + 1 <= WW - 1);
    bool vy0 = (y0 >= 0) & (y0 <= HH - 1);
    bool vy1 = (y0 + 1 >= 0) & (y0 + 1 <= HH - 1);
    float c00 = (vx0 && vy0) ? (1.f - wx) * (1.f - wy) : 0.f;
    float c01 = (vx1 && vy0) ? wx * (1.f - wy) : 0.f;
    float c10 = (vx0 && vy1) ? (1.f - wx) * wy : 0.f;
    float c11 = (vx1 && vy1) ? wx * wy : 0.f;
    int xc0 = min(max(x0, 0), WW - 1), xc1 = min(max(x0 + 1, 0), WW - 1);
    int yc0 = min(max(y0, 0), HH - 1), yc1 = min(max(y0 + 1, 0), HH - 1);
    const float4* p = (const float4*)src_t;
    size_t b = (size_t)(n << 14);
    float4 v00 = p[(b + (yc0 << 7) + xc0) * 64 + chan4];
    float4 v01 = p[(b + (yc0 << 7) + xc1) * 64 + chan4];
    float4 v10 = p[(b + (yc1 << 7) + xc0) * 64 + chan4];
    float4 v11 = p[(b + (yc1 << 7) + xc1) * 64 + chan4];
    float4 r;
    r.x = v00.x * c00 + v01.x * c01 + v10.x * c10 + v11.x * c11;
    r.y = v00.y * c00 + v01.y * c01 + v10.y * c10 + v11.y * c11;
    r.z = v00.z * c00 + v01.z * c01 + v10.z * c10 + v11.z * c11;
    r.w = v00.w * c00 + v01.w * c01 + v10.w * c10 + v11.w * c11;
    return r;
}

#define OG_SMEM ((16384 + 64 * 33) * 4)
__global__ void offgrid_kernel(const float* __restrict__ redim, const float* __restrict__ fdir,
                               const float* __restrict__ fdist, const float* __restrict__ Wofft,
                               const float* __restrict__ boff, const float* __restrict__ cp_t,
                               const float* __restrict__ spup_t, float* __restrict__ out) {
    extern __shared__ float ogs[];
    float* buf   = ogs;                 // phase A: [192][64]; phase B: [256][64]
    float* off_s = ogs + 16384;         // [64][33]
    int t   = threadIdx.x;
    int qb  = blockIdx.x * 64;
    int n   = qb >> 14;
    int hwb = qb & (HWD - 1);
    int lane = t & 31, wid = t >> 5;

    // phase A: stage concat(redim, fdir, fdist) tile [192][64]
    for (int i = t; i < 192 * 64; i += 256) {
        int ci = i >> 6; int px = i & 63; int hw = hwb + px;
        float v;
        if (ci < 128)      v = redim[(size_t)((n * C2 + ci) << 14) + hw];
        else if (ci < 160) v = fdir[(size_t)((n * 32 + ci - 128) << 14) + hw];
        else               v = fdist[(size_t)((n * 32 + ci - 160) << 14) + hw];
        buf[i] = v;
    }
    __syncthreads();
    // off GEMM: warp = co-quad (wid), lanes = px, both 32-px halves share weight regs
    {
        float a0 = 0.f, a1 = 0.f, a2 = 0.f, a3 = 0.f;
        float b0 = 0.f, b1 = 0.f, b2 = 0.f, b3 = 0.f;
        const float4* wt = (const float4*)Wofft;
        #pragma unroll 4
        for (int ci = 0; ci < 192; ci++) {
            float4 wv = __ldg(&wt[ci * 8 + wid]);
            float x0 = buf[ci * 64 + lane];
            float x1 = buf[ci * 64 + 32 + lane];
            a0 += wv.x * x0; a1 += wv.y * x0; a2 += wv.z * x0; a3 += wv.w * x0;
            b0 += wv.x * x1; b1 += wv.y * x1; b2 += wv.z * x1; b3 += wv.w * x1;
        }
        float c0 = __ldg(&boff[wid * 4 + 0]), c1 = __ldg(&boff[wid * 4 + 1]);
        float c2 = __ldg(&boff[wid * 4 + 2]), c3 = __ldg(&boff[wid * 4 + 3]);
        off_s[lane * 33 + wid * 4 + 0] = a0 + c0;
        off_s[lane * 33 + wid * 4 + 1] = a1 + c1;
        off_s[lane * 33 + wid * 4 + 2] = a2 + c2;
        off_s[lane * 33 + wid * 4 + 3] = a3 + c3;
        off_s[(lane + 32) * 33 + wid * 4 + 0] = b0 + c0;
        off_s[(lane + 32) * 33 + wid * 4 + 1] = b1 + c1;
        off_s[(lane + 32) * 33 + wid * 4 + 2] = b2 + c2;
        off_s[(lane + 32) * 33 + wid * 4 + 3] = b3 + c3;
    }
    __syncthreads();

    // phase B: warp = group; lane = (sub-pixel 0..3, chan4 0..7)
    int gi = wid;
    int cc4  = lane & 7; int sub = lane >> 3;
    const float K = 127.0f / 256.0f;
    for (int it = 0; it < 16; it++) {
        int px = it * 4 + sub;
        int hw = hwb + px;
        int ox = hw & 127, oy = hw >> 7;
        float olx = off_s[px * 33 + 2 * gi],      oly = off_s[px * 33 + 2 * gi + 1];
        float ohx = off_s[px * 33 + 16 + 2 * gi], ohy = off_s[px * 33 + 16 + 2 * gi + 1];
        int chan4 = gi * 8 + cc4;
        float4 a = sample32(cp_t,   n, chan4, (float)ox + olx * K, (float)oy + oly * K);
        float4 b = sample32(spup_t, n, chan4, (float)ox + ohx * K, (float)oy + ohy * K);
        int cbase = (gi * 32 + cc4 * 4) * 64 + px;
        buf[cbase + 0]   = a.x + b.x;
        buf[cbase + 64]  = a.y + b.y;
        buf[cbase + 128] = a.z + b.z;
        buf[cbase + 192] = a.w + b.w;
    }
    __syncthreads();
    // coalesced output store
    for (int i = t; i < 256 * 64; i += 256) {
        int c = i >> 6; int px = i & 63;
        out[(size_t)((n * 256 + c) << 14) + hwb + px] = buf[i];
    }
}

// ---------------- launch ----------------
extern "C" void kernel_launch(void* const* d_in, const int* in_sizes, int n_in,
                              void* d_out, int out_size) {
    const float* cp      = (const float*)d_in[0];
    const float* sp      = (const float*)d_in[1];
    const float* w_cp    = (const float*)d_in[2];
    const float* gm_cp   = (const float*)d_in[3];
    const float* b_cp    = (const float*)d_in[4];
    const float* w_sp    = (const float*)d_in[5];
    const float* gm_sp   = (const float*)d_in[6];
    const float* b_sp    = (const float*)d_in[7];
    const float* w_redim = (const float*)d_in[8];
    const float* b_redim = (const float*)d_in[9];
    const float* w_dir   = (const float*)d_in[10];
    const float* b_dir   = (const float*)d_in[11];
    const float* w_dist  = (const float*)d_in[12];
    const float* b_dist  = (const float*)d_in[13];
    const float* w_off   = (const float*)d_in[14];
    const float* b_off   = (const float*)d_in[15];
    float* out = (float*)d_out;

    float* sp_t   = nullptr; cudaGetSymbolAddress((void**)&sp_t,   g_sp_t);
    float* cp_t   = nullptr; cudaGetSymbolAddress((void**)&cp_t,   g_cp_t);
    float* spup_t = nullptr; cudaGetSymbolAddress((void**)&spup_t, g_spup_t);
    float* zlo    = nullptr; cudaGetSymbolAddress((void**)&zlo,    g_z);
    float* cp1    = nullptr; cudaGetSymbolAddress((void**)&cp1,    g_cp1);
    float* sp1    = nullptr; cudaGetSymbolAddress((void**)&sp1,    g_sp1);
    float* redim  = nullptr; cudaGetSymbolAddress((void**)&redim,  g_redim);
    float* sim    = nullptr; cudaGetSymbolAddress((void**)&sim,    g_sim);
    float* fdif   = nullptr; cudaGetSymbolAddress((void**)&fdif,   g_fdif);
    float* fdir   = nullptr; cudaGetSymbolAddress((void**)&fdir,   g_fdir);
    float* fdist  = nullptr; cudaGetSymbolAddress((void**)&fdist,  g_fdist);
    float* wofft  = nullptr; cudaGetSymbolAddress((void**)&wofft,  g_wofft);

    cudaFuncSetAttribute(offgrid_kernel,
                         cudaFuncAttributeMaxDynamicSharedMemorySize, OG_SMEM);

    // sampler-path transposes + NHWC upsample
    transpose_kernel<<<dim3(HWD / 32, CIN / 32, NB), 256>>>(cp, cp_t, CIN, HWD);
    transpose_kernel<<<dim3(SHW / 32, CIN / 32, NB), 256>>>(sp, sp_t, CIN, SHW);
    woff_transpose_kernel<<<24, 256>>>(w_off, wofft);
    upsample_kernel<<<(NB * HWD * 64) / 256, 256>>>(sp_t, spup_t);

    // z = affine_bn(conv1x1(sp)) at 64x64   (relu deferred to after upsample)
    conv1x1_kernel<<<dim3((NB * SHW) / 128, 1), 256>>>(sp, nullptr, CIN, CIN, 12, w_sp,
                                                       gm_sp, b_sp, -1, zlo, C2);
    // sp1 = relu(upsample(z))   — exact: conv+BN commute with bilinear interp
    upsample_relu_kernel<<<(NB * C2 * HWD) / 256, 256>>>(zlo, sp1);
    // cp1 = bn_relu(conv1x1(cp))
    conv1x1_kernel<<<dim3(NHW / 128, 1), 256>>>(cp, nullptr, CIN, CIN, 14, w_cp,
                                                gm_cp, b_cp, 1, cp1, C2);
    // redim = conv1x1(concat(cp1, sp1)) + b
    conv1x1_kernel<<<dim3(NHW / 128, 1), 256>>>(cp1, sp1, C2, 2 * C2, 14, w_redim,
                                                nullptr, b_redim, 0, redim, C2);
    simfdif_kernel<<<(NB * GR * HWD) / 256, 256>>>(cp1, sp1, fdif, sim);
    conv3x3_kernel<<<dim3(WW / 32, HH / 8, NB), 256>>>(sim, w_dir, b_dir, fdir, GR);
    conv3x3_kernel<<<dim3(WW / 32, HH / 8, NB), 256>>>(fdif, w_dist, b_dist, fdist, C2);
    offgrid_kernel<<<NHW / 64, 256, OG_SMEM>>>(redim, fdir, fdist, wofft, b_off,
                                               cp_t, spup_t, out);
}

// round 14
// speedup vs baseline: 1.1566x; 1.1566x over previous
#include <cuda_runtime.h>
#include <math.h>
#include <stdint.h>

// ---------------- problem constants ----------------
#define NB     8
#define CIN    256
#define HH     128
#define WW     128
#define HWD    16384            // HH*WW
#define NHW    131072           // NB*HWD
#define C2     128
#define GR     8
#define C2G    16               // C2/GR
#define SH     64               // sp spatial
#define SHW    4096             // 64*64

// ---------------- scratch (device globals; no allocs allowed) ----------------
__device__ float g_sp_t[NB * SHW * CIN];        // sp  NHWC (sampler path)
__device__ float g_cp_t[NB * HWD * CIN];        // cp  NHWC (sampler)
__device__ float g_spup_t[NB * HWD * CIN];      // sp_up NHWC (sampler)
__device__ float g_z[NB * C2 * SHW];            // low-res conv_bn(sp) affine
__device__ float g_cp1[NB * C2 * HWD];          // NCHW
__device__ float g_sp1[NB * C2 * HWD];
__device__ float g_redim[NB * C2 * HWD];
__device__ float g_sim[NB * GR * HWD];
__device__ float g_fdif[NB * C2 * HWD];
__device__ float g_fdir[NB * 32 * HWD];
__device__ float g_fdist[NB * 32 * HWD];
__device__ float g_wofft[192 * 32];             // w_off transposed [ci][co]

// ---------------- cp.async helpers ----------------
__device__ __forceinline__ void cp_async16(float* dst, const float* src) {
    uint32_t a = (uint32_t)__cvta_generic_to_shared(dst);
    asm volatile("cp.async.cg.shared.global [%0], [%1], 16;" :: "r"(a), "l"(src));
}
#define CP_COMMIT() asm volatile("cp.async.commit_group;" ::: "memory")
#define CP_WAIT0()  asm volatile("cp.async.wait_group 0;" ::: "memory")

// ---------------- transpose NCHW -> NHWC ----------------
__global__ void transpose_kernel(const float* __restrict__ in, float* __restrict__ out,
                                 int C, int HW) {
    __shared__ float tile[32][33];
    int hwb = blockIdx.x * 32, cb = blockIdx.y * 32, n = blockIdx.z;
    int lane = threadIdx.x & 31, row = threadIdx.x >> 5;
    #pragma unroll
    for (int r = row; r < 32; r += 8)
        tile[r][lane] = in[(size_t)(n * C + cb + r) * HW + hwb + lane];
    __syncthreads();
    #pragma unroll
    for (int r = row; r < 32; r += 8)
        out[((size_t)n * HW + hwb + r) * C + cb + lane] = tile[lane][r];
}

// ---------------- transpose w_off [32][192] -> [192][32] ----------------
__global__ void woff_transpose_kernel(const float* __restrict__ w, float* __restrict__ wt) {
    int i = blockIdx.x * 256 + threadIdx.x;
    if (i < 32 * 192) {
        int co = i / 192, ci = i - co * 192;
        wt[ci * 32 + co] = w[i];
    }
}

// ---------------- bilinear upsample (align_corners) in NHWC (sampler source) ----------------
__global__ void upsample_kernel(const float* __restrict__ sp_t, float* __restrict__ out_t) {
    int idx = blockIdx.x * 256 + threadIdx.x;
    int c4 = idx & 63;
    int p  = idx >> 6;
    int hw = p & (HWD - 1);
    int n  = p >> 14;
    int oy = hw >> 7, ox = hw & 127;
    float sy = oy * (63.0f / 127.0f);
    float sx = ox * (63.0f / 127.0f);
    int y0 = (int)sy; float wy = sy - (float)y0; int y1 = min(y0 + 1, 63);
    int x0 = (int)sx; float wx = sx - (float)x0; int x1 = min(x0 + 1, 63);
    const float4* s = (const float4*)sp_t;
    size_t b = (size_t)n * SHW;
    float4 v00 = s[(b + y0 * 64 + x0) * 64 + c4];
    float4 v01 = s[(b + y0 * 64 + x1) * 64 + c4];
    float4 v10 = s[(b + y1 * 64 + x0) * 64 + c4];
    float4 v11 = s[(b + y1 * 64 + x1) * 64 + c4];
    float w00 = (1.f - wy) * (1.f - wx), w01 = (1.f - wy) * wx;
    float w10 = wy * (1.f - wx),         w11 = wy * wx;
    float4 r;
    r.x = v00.x * w00 + v01.x * w01 + v10.x * w10 + v11.x * w11;
    r.y = v00.y * w00 + v01.y * w01 + v10.y * w10 + v11.y * w11;
    r.z = v00.z * w00 + v01.z * w01 + v10.z * w10 + v11.z * w11;
    r.w = v00.w * w00 + v01.w * w01 + v10.w * w10 + v11.w * w11;
    ((float4*)out_t)[(size_t)p * 64 + c4] = r;
}

// ---------------- bilinear upsample NCHW + ReLU (sp1 = relu(interp(z))) ----------------
__global__ void upsample_relu_kernel(const float* __restrict__ z, float* __restrict__ out) {
    int idx = blockIdx.x * 256 + threadIdx.x;
    int hw = idx & (HWD - 1);
    int nc = idx >> 14;
    int oy = hw >> 7, ox = hw & 127;
    float sy = oy * (63.0f / 127.0f);
    float sx = ox * (63.0f / 127.0f);
    int y0 = (int)sy; float wy = sy - (float)y0; int y1 = min(y0 + 1, 63);
    int x0 = (int)sx; float wx = sx - (float)x0; int x1 = min(x0 + 1, 63);
    const float* b = z + ((size_t)nc << 12);
    float v = (b[y0 * 64 + x0] * (1.f - wx) + b[y0 * 64 + x1] * wx) * (1.f - wy)
            + (b[y1 * 64 + x0] * (1.f - wx) + b[y1 * 64 + x1] * wx) * wy;
    out[idx] = fmaxf(v, 0.f);
}

// ---------------- 1x1 conv as SGEMM (NCHW) ----------------
__global__ __launch_bounds__(256, 2)
void conv1x1_kernel(const float* __restrict__ in0, const float* __restrict__ in1,
                    int ci0, int CI, int hwshift, const float* __restrict__ Wt,
                    const float* __restrict__ gamma, const float* __restrict__ beta,
                    int relu, float* __restrict__ out, int CO) {
    __shared__ __align__(16) float As[2][16][132];
    __shared__ __align__(16) float Bs[2][16][132];
    int t   = threadIdx.x;
    int qb  = blockIdx.x * 128;
    int cob = blockIdx.y * 128;
    int hwmask = (1 << hwshift) - 1;
    int n   = qb >> hwshift;
    int hwb = qb & hwmask;
    int tc  = (t & 15) * 8;
    int tr  = (t >> 4) * 8;
    int a_co = t >> 1, a_kq = (t & 1) * 8;
    int b_k  = t >> 4, b_px = (t & 15) * 8;

    float acc[8][8];
    #pragma unroll
    for (int i = 0; i < 8; i++)
        #pragma unroll
        for (int j = 0; j < 8; j++) acc[i][j] = 0.f;

    {
        int ci = b_k;
        const float* s0 = (ci < ci0)
            ? &in0[(((size_t)(n * ci0 + ci)) << hwshift) + hwb + b_px]
            : &in1[(((size_t)(n * (CI - ci0) + (ci - ci0))) << hwshift) + hwb + b_px];
        cp_async16(&Bs[0][b_k][b_px], s0);
        cp_async16(&Bs[0][b_k][b_px + 4], s0 + 4);
        CP_COMMIT();
    }
    float4 ra0 = *(const float4*)&Wt[(size_t)(cob + a_co) * CI + a_kq];
    float4 ra1 = *(const float4*)&Wt[(size_t)(cob + a_co) * CI + a_kq + 4];

    int s = 0;
    for (int kb = 0; kb < CI; kb += 16, s ^= 1) {
        As[s][a_kq + 0][a_co] = ra0.x; As[s][a_kq + 1][a_co] = ra0.y;
        As[s][a_kq + 2][a_co] = ra0.z; As[s][a_kq + 3][a_co] = ra0.w;
        As[s][a_kq + 4][a_co] = ra1.x; As[s][a_kq + 5][a_co] = ra1.y;
        As[s][a_kq + 6][a_co] = ra1.z; As[s][a_kq + 7][a_co] = ra1.w;
        CP_WAIT0();
        __syncthreads();
        int kn = kb + 16;
        if (kn < CI) {
            int ci = kn + b_k;
            const float* sn = (ci < ci0)
                ? &in0[(((size_t)(n * ci0 + ci)) << hwshift) + hwb + b_px]
                : &in1[(((size_t)(n * (CI - ci0) + (ci - ci0))) << hwshift) + hwb + b_px];
            cp_async16(&Bs[s ^ 1][b_k][b_px], sn);
            cp_async16(&Bs[s ^ 1][b_k][b_px + 4], sn + 4);
            CP_COMMIT();
            ra0 = *(const float4*)&Wt[(size_t)(cob + a_co) * CI + kn + a_kq];
            ra1 = *(const float4*)&Wt[(size_t)(cob + a_co) * CI + kn + a_kq + 4];
        }
        #pragma unroll
        for (int k = 0; k < 16; k++) {
            float4 a0 = *(const float4*)&As[s][k][tr];
            float4 a1 = *(const float4*)&As[s][k][tr + 4];
            float4 b0 = *(const float4*)&Bs[s][k][tc];
            float4 b1 = *(const float4*)&Bs[s][k][tc + 4];
            float av[8] = {a0.x, a0.y, a0.z, a0.w, a1.x, a1.y, a1.z, a1.w};
            float bv[8] = {b0.x, b0.y, b0.z, b0.w, b1.x, b1.y, b1.z, b1.w};
            #pragma unroll
            for (int i = 0; i < 8; i++)
                #pragma unroll
                for (int j = 0; j < 8; j++)
                    acc[i][j] += av[i] * bv[j];
        }
    }

    const float rs = 1.0f / sqrtf(1.0f + 1e-5f);
    #pragma unroll
    for (int i = 0; i < 8; i++) {
        int co = cob + tr + i;
        float sc = 1.f, bi;
        if (gamma) { sc = gamma[co] * rs; bi = beta[co]; } else { bi = beta[co]; }
        float r[8];
        #pragma unroll
        for (int j = 0; j < 8; j++) {
            float v = acc[i][j];
            if (gamma) { v = v * sc + bi; if (relu > 0) v = fmaxf(v, 0.f); }
            else v += bi;
            r[j] = v;
        }
        float* dst = &out[(((size_t)(n * CO + co)) << hwshift) + hwb + tc];
        *(float4*)dst       = make_float4(r[0], r[1], r[2], r[3]);
        *(float4*)(dst + 4) = make_float4(r[4], r[5], r[6], r[7]);
    }
}

// ---------------- grouped cosine sim + |cp1-sp1| (float4 over pixels) ----------------
__global__ void simfdif_kernel(const float* __restrict__ cp1, const float* __restrict__ sp1,
                               float* __restrict__ fdif, float* __restrict__ sim) {
    int idx = blockIdx.x * 256 + threadIdx.x;    // over (NB*GR*HWD)/4
    int hw4 = idx & (HWD / 4 - 1);               // pixel quad
    int ng  = idx >> 12;
    int gi = ng & 7, n = ng >> 3;
    size_t base4 = ((size_t)((n * C2 + gi * C2G) << 14) >> 2) + hw4;   // float4 index
    const float4* a4 = (const float4*)cp1;
    const float4* b4 = (const float4*)sp1;
    float4* f4 = (float4*)fdif;
    float4 num = make_float4(0.f, 0.f, 0.f, 0.f);
    float4 na  = make_float4(0.f, 0.f, 0.f, 0.f);
    float4 nb  = make_float4(0.f, 0.f, 0.f, 0.f);
    #pragma unroll
    for (int c = 0; c < C2G; c++) {
        size_t o = base4 + ((size_t)c << 12);
        float4 a = a4[o];
        float4 b = b4[o];
        num.x += a.x * b.x; num.y += a.y * b.y; num.z += a.z * b.z; num.w += a.w * b.w;
        na.x  += a.x * a.x; na.y  += a.y * a.y; na.z  += a.z * a.z; na.w  += a.w * a.w;
        nb.x  += b.x * b.x; nb.y  += b.y * b.y; nb.z  += b.z * b.z; nb.w  += b.w * b.w;
        f4[o] = make_float4(fabsf(a.x - b.x), fabsf(a.y - b.y),
                            fabsf(a.z - b.z), fabsf(a.w - b.w));
    }
    float4 r;
    r.x = num.x / (fmaxf(sqrtf(na.x), 1e-8f) * fmaxf(sqrtf(nb.x), 1e-8f));
    r.y = num.y / (fmaxf(sqrtf(na.y), 1e-8f) * fmaxf(sqrtf(nb.y), 1e-8f));
    r.z = num.z / (fmaxf(sqrtf(na.z), 1e-8f) * fmaxf(sqrtf(nb.z), 1e-8f));
    r.w = num.w / (fmaxf(sqrtf(na.w), 1e-8f) * fmaxf(sqrtf(nb.w), 1e-8f));
    ((float4*)sim)[((size_t)ng << 12) + hw4] = r;
}

// ---------------- 3x3 conv, pad 1, CO=32, register-prefetch double buffered ----------------
#define PS_ELEMS (4 * 10 * 34)   // 1360
#define WS_ELEMS (4 * 32 * 9)    // 1152
__global__ void conv3x3_kernel(const float* __restrict__ in, const float* __restrict__ wgt,
                               const float* __restrict__ bias, float* __restrict__ out, int CI) {
    __shared__ float ps[4][10][36];
    __shared__ __align__(16) float ws[4][9][32];
    int t  = threadIdx.x;
    int o  = t >> 6;
    int q  = t & 63;
    int ty = q >> 3;
    int tx = (q & 7) * 4;
    int n  = blockIdx.z;
    int y0 = blockIdx.y * 8, x0 = blockIdx.x * 32;
    float acc[8][4];
    #pragma unroll
    for (int a = 0; a < 8; a++)
        #pragma unroll
        for (int b = 0; b < 4; b++) acc[a][b] = 0.f;

    float pv[6], wv5[5];

    #pragma unroll
    for (int j = 0; j < 6; j++) {
        int i = t + j * 256;
        float v = 0.f;
        if (i < PS_ELEMS) {
            int cc = i / 340; int rem = i - cc * 340;
            int yy = rem / 34; int xx = rem - yy * 34;
            int gy = y0 + yy - 1, gx = x0 + xx - 1;
            if (gy >= 0 && gy < HH && gx >= 0 && gx < WW)
                v = in[(size_t)((n * CI + cc) << 14) + (gy << 7) + gx];
        }
        pv[j] = v;
    }
    #pragma unroll
    for (int j = 0; j < 5; j++) {
        int i = t + j * 256;
        float v = 0.f;
        if (i < WS_ELEMS) {
            int cc = i / 288; int rem = i - cc * 288;
            int tap = rem >> 5; int co = rem & 31;
            v = wgt[(size_t)(co * CI + cc) * 9 + tap];
        }
        wv5[j] = v;
    }

    for (int cb = 0; cb < CI; cb += 4) {
        __syncthreads();
        #pragma unroll
        for (int j = 0; j < 6; j++) {
            int i = t + j * 256;
            if (i < PS_ELEMS) {
                int cc = i / 340; int rem = i - cc * 340;
                int yy = rem / 34; int xx = rem - yy * 34;
                ps[cc][yy][xx] = pv[j];
            }
        }
        #pragma unroll
        for (int j = 0; j < 5; j++) {
            int i = t + j * 256;
            if (i < WS_ELEMS) {
                int cc = i / 288; int rem = i - cc * 288;
                int tap = rem >> 5; int co = rem & 31;
                ws[cc][tap][co] = wv5[j];
            }
        }
        __syncthreads();
        int cn = cb + 4;
        if (cn < CI) {
            #pragma unroll
            for (int j = 0; j < 6; j++) {
                int i = t + j * 256;
                float v = 0.f;
                if (i < PS_ELEMS) {
                    int cc = i / 340; int rem = i - cc * 340;
                    int yy = rem / 34; int xx = rem - yy * 34;
                    int gy = y0 + yy - 1, gx = x0 + xx - 1;
                    if (gy >= 0 && gy < HH && gx >= 0 && gx < WW)
                        v = in[(size_t)((n * CI + cn + cc) << 14) + (gy << 7) + gx];
                }
                pv[j] = v;
            }
            #pragma unroll
            for (int j = 0; j < 5; j++) {
                int i = t + j * 256;
                float v = 0.f;
                if (i < WS_ELEMS) {
                    int cc = i / 288; int rem = i - cc * 288;
                    int tap = rem >> 5; int co = rem & 31;
                    v = wgt[(size_t)(co * CI + cn + cc) * 9 + tap];
                }
                wv5[j] = v;
            }
        }
        #pragma unroll
        for (int cc = 0; cc < 4; cc++) {
            float p[3][6];
            #pragma unroll
            for (int yy = 0; yy < 3; yy++)
                #pragma unroll
                for (int xx = 0; xx < 6; xx++)
                    p[yy][xx] = ps[cc][ty + yy][tx + xx];
            #pragma unroll
            for (int tap = 0; tap < 9; tap++) {
                int ky = tap / 3, kx = tap - ky * 3;
                float4 w0 = *(const float4*)&ws[cc][tap][o * 8];
                float4 w1 = *(const float4*)&ws[cc][tap][o * 8 + 4];
                float wv[8] = {w0.x, w0.y, w0.z, w0.w, w1.x, w1.y, w1.z, w1.w};
                #pragma unroll
                for (int c8 = 0; c8 < 8; c8++) {
                    acc[c8][0] += wv[c8] * p[ky][kx + 0];
                    acc[c8][1] += wv[c8] * p[ky][kx + 1];
                    acc[c8][2] += wv[c8] * p[ky][kx + 2];
                    acc[c8][3] += wv[c8] * p[ky][kx + 3];
                }
            }
        }
    }
    #pragma unroll
    for (int c8 = 0; c8 < 8; c8++) {
        int co = o * 8 + c8;
        float b = bias[co];
        size_t ob = (size_t)((n * 32 + co) << 14) + ((y0 + ty) << 7) + x0 + tx;
        #pragma unroll
        for (int j = 0; j < 4; j++) out[ob + j] = acc[c8][j] + b;
    }
}

// ---------------- fused off 1x1 conv + dual grid_sample ----------------
__device__ __forceinline__ float4 sample32(const float* __restrict__ src_t, int n,
                                           int chan4, float gx, float gy) {
    float x0f = floorf(gx), y0f = floorf(gy);
    int x0 = (int)x0f, y0 = (int)y0f;
    float wx = gx - x0f, wy = gy - y0f;
    bool vx0 = (x0 >= 0) & (x0 <= WW - 1);
    bool vx1 = (x0 + 1 >= 0) & (x0 + 1 <= WW - 1);
    bool vy0 = (y0 >= 0) & (y0 <= HH - 1);
    bool vy1 = (y0 + 1 >= 0) & (y0 + 1 <= HH - 1);
    float c00 = (vx0 && vy0) ? (1.f - wx) * (1.f - wy) : 0.f;
    float c01 = (vx1 && vy0) ? wx * (1.f - wy) : 0.f;
    float c10 = (vx0 && vy1) ? (1.f - wx) * wy : 0.f;
    float c11 = (vx1 && vy1) ? wx * wy : 0.f;
    int xc0 = min(max(x0, 0), WW - 1), xc1 = min(max(x0 + 1, 0), WW - 1);
    int yc0 = min(max(y0, 0), HH - 1), yc1 = min(max(y0 + 1, 0), HH - 1);
    const float4* p = (const float4*)src_t;
    size_t b = (size_t)(n << 14);
    float4 v00 = p[(b + (yc0 << 7) + xc0) * 64 + chan4];
    float4 v01 = p[(b + (yc0 << 7) + xc1) * 64 + chan4];
    float4 v10 = p[(b + (yc1 << 7) + xc0) * 64 + chan4];
    float4 v11 = p[(b + (yc1 << 7) + xc1) * 64 + chan4];
    float4 r;
    r.x = v00.x * c00 + v01.x * c01 + v10.x * c10 + v11.x * c11;
    r.y = v00.y * c00 + v01.y * c01 + v10.y * c10 + v11.y * c11;
    r.z = v00.z * c00 + v01.z * c01 + v10.z * c10 + v11.z * c11;
    r.w = v00.w * c00 + v01.w * c01 + v10.w * c10 + v11.w * c11;
    return r;
}

__global__ void offgrid_kernel(const float* __restrict__ redim, const float* __restrict__ fdir,
                               const float* __restrict__ fdist, const float* __restrict__ Wofft,
                               const float* __restrict__ boff, const float* __restrict__ cp_t,
                               const float* __restrict__ spup_t, float* __restrict__ out) {
    __shared__ float buf[256 * 32];
    __shared__ float off_s[32][33];
    int t   = threadIdx.x;
    int qb  = blockIdx.x * 32;
    int n   = qb >> 14;
    int hwb = qb & (HWD - 1);
    int lane = t & 31, wid = t >> 5;

    for (int i = t; i < 192 * 32; i += 256) {
        int ci = i >> 5; int px = i & 31; int hw = hwb + px;
        float v;
        if (ci < 128)      v = redim[(size_t)((n * C2 + ci) << 14) + hw];
        else if (ci < 160) v = fdir[(size_t)((n * 32 + ci - 128) << 14) + hw];
        else               v = fdist[(size_t)((n * 32 + ci - 160) << 14) + hw];
        buf[i] = v;
    }
    __syncthreads();
    {
        float a0 = 0.f, a1 = 0.f, a2 = 0.f, a3 = 0.f;
        const float4* wt = (const float4*)Wofft;
        #pragma unroll 4
        for (int ci = 0; ci < 192; ci++) {
            float4 wv = __ldg(&wt[ci * 8 + wid]);
            float x = buf[ci * 32 + lane];
            a0 += wv.x * x; a1 += wv.y * x; a2 += wv.z * x; a3 += wv.w * x;
        }
        off_s[lane][wid * 4 + 0] = a0 + __ldg(&boff[wid * 4 + 0]);
        off_s[lane][wid * 4 + 1] = a1 + __ldg(&boff[wid * 4 + 1]);
        off_s[lane][wid * 4 + 2] = a2 + __ldg(&boff[wid * 4 + 2]);
        off_s[lane][wid * 4 + 3] = a3 + __ldg(&boff[wid * 4 + 3]);
    }
    __syncthreads();

    int gi = wid;
    int cc4  = lane & 7; int sub = lane >> 3;
    const float K = 127.0f / 256.0f;
    for (int it = 0; it < 8; it++) {
        int px = it * 4 + sub;
        int hw = hwb + px;
        int ox = hw & 127, oy = hw >> 7;
        float olx = off_s[px][2 * gi],      oly = off_s[px][2 * gi + 1];
        float ohx = off_s[px][16 + 2 * gi], ohy = off_s[px][16 + 2 * gi + 1];
        int chan4 = gi * 8 + cc4;
        float4 a = sample32(cp_t,   n, chan4, (float)ox + olx * K, (float)oy + oly * K);
        float4 b = sample32(spup_t, n, chan4, (float)ox + ohx * K, (float)oy + ohy * K);
        int cbase = (gi * 32 + cc4 * 4) * 32 + px;
        buf[cbase + 0]  = a.x + b.x;
        buf[cbase + 32] = a.y + b.y;
        buf[cbase + 64] = a.z + b.z;
        buf[cbase + 96] = a.w + b.w;
    }
    __syncthreads();
    for (int i = t; i < 256 * 32; i += 256) {
        int c = i >> 5; int px = i & 31;
        out[(size_t)((n * 256 + c) << 14) + hwb + px] = buf[i];
    }
}

// ---------------- launch ----------------
extern "C" void kernel_launch(void* const* d_in, const int* in_sizes, int n_in,
                              void* d_out, int out_size) {
    const float* cp      = (const float*)d_in[0];
    const float* sp      = (const float*)d_in[1];
    const float* w_cp    = (const float*)d_in[2];
    const float* gm_cp   = (const float*)d_in[3];
    const float* b_cp    = (const float*)d_in[4];
    const float* w_sp    = (const float*)d_in[5];
    const float* gm_sp   = (const float*)d_in[6];
    const float* b_sp    = (const float*)d_in[7];
    const float* w_redim = (const float*)d_in[8];
    const float* b_redim = (const float*)d_in[9];
    const float* w_dir   = (const float*)d_in[10];
    const float* b_dir   = (const float*)d_in[11];
    const float* w_dist  = (const float*)d_in[12];
    const float* b_dist  = (const float*)d_in[13];
    const float* w_off   = (const float*)d_in[14];
    const float* b_off   = (const float*)d_in[15];
    float* out = (float*)d_out;

    float* sp_t   = nullptr; cudaGetSymbolAddress((void**)&sp_t,   g_sp_t);
    float* cp_t   = nullptr; cudaGetSymbolAddress((void**)&cp_t,   g_cp_t);
    float* spup_t = nullptr; cudaGetSymbolAddress((void**)&spup_t, g_spup_t);
    float* zlo    = nullptr; cudaGetSymbolAddress((void**)&zlo,    g_z);
    float* cp1    = nullptr; cudaGetSymbolAddress((void**)&cp1,    g_cp1);
    float* sp1    = nullptr; cudaGetSymbolAddress((void**)&sp1,    g_sp1);
    float* redim  = nullptr; cudaGetSymbolAddress((void**)&redim,  g_redim);
    float* sim    = nullptr; cudaGetSymbolAddress((void**)&sim,    g_sim);
    float* fdif   = nullptr; cudaGetSymbolAddress((void**)&fdif,   g_fdif);
    float* fdir   = nullptr; cudaGetSymbolAddress((void**)&fdir,   g_fdir);
    float* fdist  = nullptr; cudaGetSymbolAddress((void**)&fdist,  g_fdist);
    float* wofft  = nullptr; cudaGetSymbolAddress((void**)&wofft,  g_wofft);

    // sampler-path transposes + NHWC upsample
    transpose_kernel<<<dim3(HWD / 32, CIN / 32, NB), 256>>>(cp, cp_t, CIN, HWD);
    transpose_kernel<<<dim3(SHW / 32, CIN / 32, NB), 256>>>(sp, sp_t, CIN, SHW);
    woff_transpose_kernel<<<24, 256>>>(w_off, wofft);
    upsample_kernel<<<(NB * HWD * 64) / 256, 256>>>(sp_t, spup_t);

    // z = affine_bn(conv1x1(sp)) at 64x64   (relu deferred to after upsample)
    conv1x1_kernel<<<dim3((NB * SHW) / 128, 1), 256>>>(sp, nullptr, CIN, CIN, 12, w_sp,
                                                       gm_sp, b_sp, -1, zlo, C2);
    // sp1 = relu(upsample(z))   — exact: conv+BN commute with bilinear interp
    upsample_relu_kernel<<<(NB * C2 * HWD) / 256, 256>>>(zlo, sp1);
    // cp1 = bn_relu(conv1x1(cp))
    conv1x1_kernel<<<dim3(NHW / 128, 1), 256>>>(cp, nullptr, CIN, CIN, 14, w_cp,
                                                gm_cp, b_cp, 1, cp1, C2);
    // redim = conv1x1(concat(cp1, sp1)) + b
    conv1x1_kernel<<<dim3(NHW / 128, 1), 256>>>(cp1, sp1, C2, 2 * C2, 14, w_redim,
                                                nullptr, b_redim, 0, redim, C2);
    simfdif_kernel<<<(NB * GR * HWD / 4) / 256, 256>>>(cp1, sp1, fdif, sim);
    conv3x3_kernel<<<dim3(WW / 32, HH / 8, NB), 256>>>(sim, w_dir, b_dir, fdir, GR);
    conv3x3_kernel<<<dim3(WW / 32, HH / 8, NB), 256>>>(fdif, w_dist, b_dist, fdist, C2);
    offgrid_kernel<<<NHW / 32, 256>>>(redim, fdir, fdist, wofft, b_off, cp_t, spup_t, out);
}